// round 16
// baseline (speedup 1.0000x reference)
#include <cuda_runtime.h>
#include <cuda_bf16.h>
#include <cuda_fp16.h>
#include <cstdint>
#include <cstddef>

// Problem constants
#define BB 2
#define SS 2048
#define DD 1024
#define HH 16
#define HDIM 64
#define MTOT (BB * SS) // 4096

#define ACT ((size_t)MTOT * DD)  // 4194304 elements
#define WN  ((size_t)DD * DD)    // 1048576 elements

// ---------------------------------------------------------------------------
// Scratch (device globals)
// ---------------------------------------------------------------------------
__device__ int g_idx[MTOT];
__device__ int g_cnt[BB];
__device__ __half g_q[MTOT * DD];          // fp16 activations
__device__ __half g_k[MTOT * DD];
__device__ __half g_v[MTOT * DD];
__device__ __half g_W[4][2 * DD * DD];     // fp16 hi/lo weights (lo at +WN)
__device__ __half g_pq[MTOT * DD];         // projected Q/K/V, fp16 single-plane
__device__ __half g_pk[MTOT * DD];
__device__ __half g_pv[MTOT * DD];
__device__ __half g_a[MTOT * DD];          // attention output, fp16

// ---------------------------------------------------------------------------
// PTX helpers
// ---------------------------------------------------------------------------
__device__ __forceinline__ void cp16(unsigned dst, const void* src) {
    asm volatile("cp.async.cg.shared.global [%0], [%1], 16;" :: "r"(dst), "l"(src));
}
__device__ __forceinline__ void cp_commit() { asm volatile("cp.async.commit_group;"); }
__device__ __forceinline__ void cp_wait0()  { asm volatile("cp.async.wait_group 0;" ::: "memory"); }

__device__ __forceinline__ void ldmx4(uint32_t* r, uint32_t addr) {
    asm volatile("ldmatrix.sync.aligned.m8n8.x4.shared.b16 {%0,%1,%2,%3}, [%4];"
                 : "=r"(r[0]), "=r"(r[1]), "=r"(r[2]), "=r"(r[3]) : "r"(addr));
}
__device__ __forceinline__ void ldmx4t(uint32_t* r, uint32_t addr) {
    asm volatile("ldmatrix.sync.aligned.m8n8.x4.trans.shared.b16 {%0,%1,%2,%3}, [%4];"
                 : "=r"(r[0]), "=r"(r[1]), "=r"(r[2]), "=r"(r[3]) : "r"(addr));
}
__device__ __forceinline__ void mma_f16(float* d, const uint32_t* a, const uint32_t* b) {
    asm volatile(
        "mma.sync.aligned.m16n8k16.row.col.f32.f16.f16.f32 "
        "{%0,%1,%2,%3}, {%4,%5,%6,%7}, {%8,%9}, {%0,%1,%2,%3};"
        : "+f"(d[0]), "+f"(d[1]), "+f"(d[2]), "+f"(d[3])
        : "r"(a[0]), "r"(a[1]), "r"(a[2]), "r"(a[3]), "r"(b[0]), "r"(b[1]));
}
__device__ __forceinline__ float ex2(float x) {
    float r;
    asm("ex2.approx.f32 %0, %1;" : "=f"(r) : "f"(x));
    return r;
}

// ---------------------------------------------------------------------------
// Conv kernels: fp32 -> fp16 single (activations), fp32 -> fp16 hi/lo (weights)
// ---------------------------------------------------------------------------
struct ConvHArgs {
    const float* src[4];
    __half* dst[4];
};
__global__ __launch_bounds__(256) void conv_half_multi(ConvHArgs a, int n8)
{
    int i = blockIdx.x * blockDim.x + threadIdx.x;
    if (i >= n8) return;
    const int y = blockIdx.y;
    const float* x = a.src[y];
    float4 v0 = ((const float4*)x)[2 * i];
    float4 v1 = ((const float4*)x)[2 * i + 1];
    __half2 h0 = __floats2half2_rn(v0.x, v0.y);
    __half2 h1 = __floats2half2_rn(v0.z, v0.w);
    __half2 h2 = __floats2half2_rn(v1.x, v1.y);
    __half2 h3 = __floats2half2_rn(v1.z, v1.w);
    ((uint4*)a.dst[y])[i] = make_uint4(*(uint32_t*)&h0, *(uint32_t*)&h1,
                                       *(uint32_t*)&h2, *(uint32_t*)&h3);
}

struct ConvWArgs {
    const float* src[4];
    __half* hi[4];
    __half* lo[4];
};
__global__ __launch_bounds__(256) void conv_wsplit_multi(ConvWArgs a, int n8)
{
    int i = blockIdx.x * blockDim.x + threadIdx.x;
    if (i >= n8) return;
    const int y = blockIdx.y;
    const float* x = a.src[y];
    float4 v0 = ((const float4*)x)[2 * i];
    float4 v1 = ((const float4*)x)[2 * i + 1];
    float f[8] = {v0.x, v0.y, v0.z, v0.w, v1.x, v1.y, v1.z, v1.w};
    uint32_t hp[4], lp[4];
#pragma unroll
    for (int j = 0; j < 4; j++) {
        __half h0 = __float2half_rn(f[2 * j]);
        __half h1 = __float2half_rn(f[2 * j + 1]);
        __half l0 = __float2half_rn(f[2 * j] - __half2float(h0));
        __half l1 = __float2half_rn(f[2 * j + 1] - __half2float(h1));
        __half2 hv(h0, h1), lv(l0, l1);
        hp[j] = *(uint32_t*)&hv;
        lp[j] = *(uint32_t*)&lv;
    }
    ((uint4*)a.hi[y])[i] = make_uint4(hp[0], hp[1], hp[2], hp[3]);
    ((uint4*)a.lo[y])[i] = make_uint4(lp[0], lp[1], lp[2], lp[3]);
}

// ---------------------------------------------------------------------------
// Kernel 1: deterministic mask compaction
// ---------------------------------------------------------------------------
__global__ __launch_bounds__(1024) void build_idx_kernel(
    const int* __restrict__ kp, const int* __restrict__ am,
    int* __restrict__ idx, int* __restrict__ counts)
{
    __shared__ int ssum[1024];
    const int b = blockIdx.x;
    const int t = threadIdx.x;
    const int base = b * SS;
    const int s0 = 2 * t, s1 = 2 * t + 1;
    int v0 = (kp[base + s0] == 0 && am[base + s0] == 0) ? 1 : 0;
    int v1 = (kp[base + s1] == 0 && am[base + s1] == 0) ? 1 : 0;
    ssum[t] = v0 + v1;
    __syncthreads();
    for (int off = 1; off < 1024; off <<= 1) {
        int add = (t >= off) ? ssum[t - off] : 0;
        int val = ssum[t];
        __syncthreads();
        ssum[t] = val + add;
        __syncthreads();
    }
    int excl = ssum[t] - (v0 + v1);
    if (v0) idx[base + excl]      = base + s0;
    if (v1) idx[base + excl + v0] = base + s1;
    if (t == 1023) counts[b] = ssum[1023];
}

// ---------------------------------------------------------------------------
// Kernel 2: f16 HMMA GEMM, tile 256x128, BK=64, 512 threads.
// A fragments loaded DIRECTLY from gmem via LDG.32 (m16k16 lane layout is
// 4B-contiguous in row-major A) with 1-ks-ahead register prefetch — no A smem.
// W = fp16 hi/lo staged via cp.async (shared 8x across warps).
// Smem per stage: Wh 16K | Wl 16K = 32KB; x2 stages = 64KB.
// ---------------------------------------------------------------------------
#define GSTAGE2 32768
#define GSM2_BYTES (2 * GSTAGE2)

__global__ __launch_bounds__(512, 1) void gemm_mma_kernel(
    const __half* __restrict__ A0, const __half* __restrict__ A1,
    const __half* __restrict__ A2,
    const __half* __restrict__ Wb,          // weight z at Wb + z*2*WN; lo at +WN
    const float* __restrict__ b0, const float* __restrict__ b1,
    const float* __restrict__ b2,
    float s0,
    float* __restrict__ Cf,
    __half* __restrict__ C0, __half* __restrict__ C1, __half* __restrict__ C2,
    const int* __restrict__ gather, const int* __restrict__ counts, int gmask)
{
    extern __shared__ char smem[];
    const uint32_t sb = (uint32_t)__cvta_generic_to_shared(smem);
    const int z = blockIdx.z;
    const __half* Ain = (z == 0) ? A0 : (z == 1) ? A1 : A2;
    const __half* Whi = Wb + (size_t)z * 2 * WN;
    const float* bias = (z == 0) ? b0 : (z == 1) ? b1 : b2;
    __half* Ch = (z == 0) ? C0 : (z == 1) ? C1 : C2;
    const float scale = (z == 0) ? s0 : 1.0f;
    const bool useG = ((gmask >> z) & 1) != 0;

    const int nBase = blockIdx.x * 128;
    const int mBase = blockIdx.y * 256;
    int cnt = 0;
    if (useG) {
        cnt = counts[mBase >> 11];
        if ((mBase & 2047) >= cnt) return;
    }
    const int t = threadIdx.x;
    const int wid = t >> 5, lane = t & 31;
    const int wm = wid >> 1;
    const int wn = wid & 1;

    // W staging: row t>>2 (0..127), units (t&3)*2 + i, both planes
    const int sRowW = t >> 2, uW = (t & 3) * 2;
    const __half* bHp = Whi + (size_t)(nBase + sRowW) * DD;

    // W fragment geometry (unchanged)
    const int g  = lane >> 3;
    const int lr = lane & 7;
    const uint32_t rowB = wn * 64 + (g >> 1) * 8 + lr;
    const uint32_t rxb  = rowB & 7;
    const uint32_t boff = rowB * 128;
    const int bU = g & 1;

    // ---- A fragment row pointers (per-lane direct-gmem; gather resolved once)
    const __half* pA[2][2]; // [mt][m-half]
#pragma unroll
    for (int mt = 0; mt < 2; mt++) {
#pragma unroll
        for (int hh = 0; hh < 2; hh++) {
            int m = mBase + wm * 32 + mt * 16 + hh * 8 + (lane >> 2);
            int r;
            if (useG) {
                bool ok = (m & 2047) < cnt;
                r = ok ? gather[m] : ((m >> 11) * SS); // safe dummy row
            } else {
                r = m;
            }
            pA[mt][hh] = Ain + (size_t)r * DD + 2 * (lane & 3);
        }
    }

    float acc[2][8][4];
#pragma unroll
    for (int mt = 0; mt < 2; mt++)
#pragma unroll
        for (int j = 0; j < 8; j++)
#pragma unroll
            for (int r = 0; r < 4; r++) acc[mt][j][r] = 0.f;

    auto stage = [&](int s, int k0) {
        const uint32_t bb = sb + s * GSTAGE2;
#pragma unroll
        for (int i = 0; i < 2; i++) {
            int u = uW + i;
            uint32_t sw = sRowW * 128 + ((u ^ (sRowW & 7)) << 4);
            cp16(bb +         sw, bHp + k0 + u * 8);
            cp16(bb + 16384 + sw, bHp + WN + k0 + u * 8);
        }
        cp_commit();
    };

    // A fragment double-buffer (prefetch one ks ahead)
    uint32_t aB[2][2][4]; // [buf][mt][reg]
    auto loadA = [&](uint32_t a[2][4], int kk) {
#pragma unroll
        for (int mt = 0; mt < 2; mt++) {
            a[mt][0] = *(const uint32_t*)(pA[mt][0] + kk);
            a[mt][1] = *(const uint32_t*)(pA[mt][1] + kk);
            a[mt][2] = *(const uint32_t*)(pA[mt][0] + kk + 8);
            a[mt][3] = *(const uint32_t*)(pA[mt][1] + kk + 8);
        }
    };
    int ab = 0;
    loadA(aB[0], 0);
    stage(0, 0);

    for (int c = 0; c < 16; c++) {
        cp_wait0();
        __syncthreads();
        if (c + 1 < 16) stage((c + 1) & 1, (c + 1) * 64);

        const uint32_t base = sb + (c & 1) * GSTAGE2;
#pragma unroll
        for (int ks = 0; ks < 4; ks++) {
            // prefetch next ks's A fragments (skip only at the very end)
            if (!(c == 15 && ks == 3)) {
                int nk = (ks == 3) ? (c + 1) * 64 : c * 64 + (ks + 1) * 16;
                loadA(aB[ab ^ 1], nk);
            }
            const uint32_t (*aC)[4] = aB[ab];
#pragma unroll
            for (int jp = 0; jp < 4; jp++) {
                uint32_t sw = ((2 * ks + bU) ^ rxb) << 4;
                uint32_t rh[4], rl[4];
                ldmx4(rh, base +         boff + jp * 2048 + sw);
                ldmx4(rl, base + 16384 + boff + jp * 2048 + sw);
                mma_f16(acc[0][2 * jp],     aC[0], rh);
                mma_f16(acc[1][2 * jp],     aC[1], rh);
                mma_f16(acc[0][2 * jp + 1], aC[0], rh + 2);
                mma_f16(acc[1][2 * jp + 1], aC[1], rh + 2);
                mma_f16(acc[0][2 * jp],     aC[0], rl);
                mma_f16(acc[1][2 * jp],     aC[1], rl);
                mma_f16(acc[0][2 * jp + 1], aC[0], rl + 2);
                mma_f16(acc[1][2 * jp + 1], aC[1], rl + 2);
            }
            ab ^= 1;
        }
        __syncthreads();
    }

#pragma unroll
    for (int mt = 0; mt < 2; mt++) {
        int m0 = mBase + wm * 32 + mt * 16 + (lane >> 2);
        int m1 = m0 + 8;
        bool ok0 = true, ok1 = true;
        if (useG) {
            ok0 = (m0 & 2047) < cnt;
            ok1 = (m1 & 2047) < cnt;
        }
#pragma unroll
        for (int j = 0; j < 8; j++) {
            int n = nBase + wn * 64 + j * 8 + 2 * (lane & 3);
            float b0v = bias[n], b1v = bias[n + 1];
            float o00 = (acc[mt][j][0] + b0v) * scale;
            float o01 = (acc[mt][j][1] + b1v) * scale;
            float o10 = (acc[mt][j][2] + b0v) * scale;
            float o11 = (acc[mt][j][3] + b1v) * scale;
            if (Cf) {
                if (ok0) *(float2*)&Cf[(size_t)m0 * DD + n] = make_float2(o00, o01);
                if (ok1) *(float2*)&Cf[(size_t)m1 * DD + n] = make_float2(o10, o11);
            } else {
                if (ok0) *(__half2*)&Ch[(size_t)m0 * DD + n] = __floats2half2_rn(o00, o01);
                if (ok1) *(__half2*)&Ch[(size_t)m1 * DD + n] = __floats2half2_rn(o10, o11);
            }
        }
    }
}

// ---------------------------------------------------------------------------
// Kernel 3: tensor-core flash attention — fp16 single-plane Q/K/V/P.
// (unchanged from round 15)
// ---------------------------------------------------------------------------
#define ASM_K 0
#define ASM_V 16384
#define ATTN_SMEM 32768

__global__ __launch_bounds__(256, 2) void attn_mma_kernel(
    const __half* __restrict__ Q_, const __half* __restrict__ K_,
    const __half* __restrict__ V_, __half* __restrict__ O_,
    const int* __restrict__ counts)
{
    extern __shared__ char smem[];
    const uint32_t sb = (uint32_t)__cvta_generic_to_shared(smem);
    const int qb = blockIdx.x, h = blockIdx.y, b = blockIdx.z;
    const int t = threadIdx.x, w = t >> 5, lane = t & 31;
    const int q0 = qb * 128;
    const int cnt = counts[b];
    const int nb = (cnt + 63) >> 6;
    const size_t hoff = (size_t)h * HDIM;

    const int g  = lane >> 3;
    const int lr = lane & 7;
    const uint32_t rowA = w * 16 + (g & 1) * 8 + lr;
    const uint32_t rxa  = rowA & 7;
    const uint32_t aoff = rowA * 128;
    const int aU = g >> 1;
    const uint32_t rowB = (g >> 1) * 8 + lr;
    const uint32_t rxb  = rowB & 7;
    const int bU = g & 1;
    const uint32_t rowV = (g & 1) * 8 + lr;
    const uint32_t rxv  = rowV & 7;
    const int vU = g >> 1;

    {
        const int sRowQ = t >> 1, uBQ = (t & 1) * 4;
        const __half* qp = Q_ + (size_t)(b * SS + q0 + sRowQ) * DD + hoff;
#pragma unroll
        for (int i = 0; i < 4; i++) {
            int u = uBQ + i;
            uint32_t off = sRowQ * 128 + ((u ^ (sRowQ & 7)) << 4);
            cp16(sb + off, qp + u * 8);
        }
        cp_commit();
    }
    cp_wait0();
    __syncthreads();

    uint32_t qa[4][4];
#pragma unroll
    for (int ks = 0; ks < 4; ks++) {
        const uint32_t swA = ((2 * ks + aU) ^ rxa) << 4;
        ldmx4(qa[ks], sb + aoff + swA);
    }
    __syncthreads();

    const int sRowK = t >> 2, uBK = (t & 3) * 2;
    auto stage_kv = [&](int bufI, int kbase) {
        const size_t rb = (size_t)(b * SS + kbase + sRowK) * DD + hoff;
        const uint32_t o = bufI * 8192;
#pragma unroll
        for (int i = 0; i < 2; i++) {
            int u = uBK + i;
            uint32_t sw = sRowK * 128 + ((u ^ (sRowK & 7)) << 4);
            cp16(sb + ASM_K + o + sw, K_ + rb + u * 8);
            cp16(sb + ASM_V + o + sw, V_ + rb + u * 8);
        }
    };
    stage_kv(0, 0);
    cp_commit();

    float m0 = -1e30f, m1 = -1e30f, l0 = 0.f, l1 = 0.f;
    float oacc[8][4];
#pragma unroll
    for (int j = 0; j < 8; j++)
#pragma unroll
        for (int r = 0; r < 4; r++) oacc[j][r] = 0.f;

    int buf = 0;
    for (int kb = 0; kb < nb; kb++) {
        cp_wait0();
        __syncthreads();
        if (kb + 1 < nb) {
            stage_kv(buf ^ 1, (kb + 1) * 64);
            cp_commit();
        }

        const uint32_t tK = sb + ASM_K + buf * 8192;

        float sacc[8][4];
#pragma unroll
        for (int j = 0; j < 8; j++)
#pragma unroll
            for (int r = 0; r < 4; r++) sacc[j][r] = 0.f;
#pragma unroll
        for (int ks = 0; ks < 4; ks++) {
#pragma unroll
            for (int jp = 0; jp < 4; jp++) {
                const uint32_t addr = (rowB + 16 * jp) * 128 + (((2 * ks + bU) ^ rxb) << 4);
                uint32_t rh[4];
                ldmx4(rh, tK + addr);
                mma_f16(sacc[2 * jp],     qa[ks], rh);
                mma_f16(sacc[2 * jp + 1], qa[ks], rh + 2);
            }
        }

        const int kcol = kb * 64 + 2 * (lane & 3);
#pragma unroll
        for (int j = 0; j < 8; j++) {
            const int kc = kcol + 8 * j;
            if (kc >= cnt)     { sacc[j][0] = -1e30f; sacc[j][2] = -1e30f; }
            if (kc + 1 >= cnt) { sacc[j][1] = -1e30f; sacc[j][3] = -1e30f; }
        }

        float rm0 = -1e30f, rm1 = -1e30f;
#pragma unroll
        for (int j = 0; j < 8; j++) {
            rm0 = fmaxf(rm0, fmaxf(sacc[j][0], sacc[j][1]));
            rm1 = fmaxf(rm1, fmaxf(sacc[j][2], sacc[j][3]));
        }
        rm0 = fmaxf(rm0, __shfl_xor_sync(0xffffffffu, rm0, 1));
        rm0 = fmaxf(rm0, __shfl_xor_sync(0xffffffffu, rm0, 2));
        rm1 = fmaxf(rm1, __shfl_xor_sync(0xffffffffu, rm1, 1));
        rm1 = fmaxf(rm1, __shfl_xor_sync(0xffffffffu, rm1, 2));
        const float nm0 = fmaxf(m0, rm0), nm1 = fmaxf(m1, rm1);
        const float c0 = ex2(m0 - nm0), c1 = ex2(m1 - nm1);
        m0 = nm0; m1 = nm1;
        float rs0 = 0.f, rs1 = 0.f;
#pragma unroll
        for (int j = 0; j < 8; j++) {
            sacc[j][0] = ex2(sacc[j][0] - nm0);
            sacc[j][1] = ex2(sacc[j][1] - nm0);
            sacc[j][2] = ex2(sacc[j][2] - nm1);
            sacc[j][3] = ex2(sacc[j][3] - nm1);
            rs0 += sacc[j][0] + sacc[j][1];
            rs1 += sacc[j][2] + sacc[j][3];
        }
        rs0 += __shfl_xor_sync(0xffffffffu, rs0, 1);
        rs0 += __shfl_xor_sync(0xffffffffu, rs0, 2);
        rs1 += __shfl_xor_sync(0xffffffffu, rs1, 1);
        rs1 += __shfl_xor_sync(0xffffffffu, rs1, 2);
        l0 = l0 * c0 + rs0;
        l1 = l1 * c1 + rs1;
#pragma unroll
        for (int j = 0; j < 8; j++) {
            oacc[j][0] *= c0; oacc[j][1] *= c0;
            oacc[j][2] *= c1; oacc[j][3] *= c1;
        }

        const uint32_t tV = sb + ASM_V + buf * 8192;
#pragma unroll
        for (int ks = 0; ks < 4; ks++) {
            const int nt0 = 2 * ks, nt1 = 2 * ks + 1;
            uint32_t aP[4];
            {
                __half2 p0 = __floats2half2_rn(sacc[nt0][0], sacc[nt0][1]);
                __half2 p1 = __floats2half2_rn(sacc[nt0][2], sacc[nt0][3]);
                __half2 p2 = __floats2half2_rn(sacc[nt1][0], sacc[nt1][1]);
                __half2 p3 = __floats2half2_rn(sacc[nt1][2], sacc[nt1][3]);
                aP[0] = *(uint32_t*)&p0; aP[1] = *(uint32_t*)&p1;
                aP[2] = *(uint32_t*)&p2; aP[3] = *(uint32_t*)&p3;
            }
#pragma unroll
            for (int dp = 0; dp < 4; dp++) {
                const uint32_t addr = (rowV + 16 * ks) * 128 + (((2 * dp + vU) ^ rxv) << 4);
                uint32_t rv[4];
                ldmx4t(rv, tV + addr);
                mma_f16(oacc[2 * dp],     aP, rv);
                mma_f16(oacc[2 * dp + 1], aP, rv + 2);
            }
        }
        buf ^= 1;
    }

    const float inv0 = 1.0f / l0, inv1 = 1.0f / l1;
    const int row0 = b * SS + q0 + w * 16 + (lane >> 2);
    const int row1 = row0 + 8;
    const int dbase = h * HDIM + 2 * (lane & 3);
#pragma unroll
    for (int j = 0; j < 8; j++) {
        size_t a0 = (size_t)row0 * DD + dbase + 8 * j;
        size_t a1 = (size_t)row1 * DD + dbase + 8 * j;
        *(__half2*)&O_[a0] = __floats2half2_rn(oacc[j][0] * inv0, oacc[j][1] * inv0);
        *(__half2*)&O_[a1] = __floats2half2_rn(oacc[j][2] * inv1, oacc[j][3] * inv1);
    }
}

// ---------------------------------------------------------------------------
// Launch
// ---------------------------------------------------------------------------
extern "C" void kernel_launch(void* const* d_in, const int* in_sizes, int n_in,
                              void* d_out, int out_size)
{
    (void)out_size;
    const float* qkv[3]   = {nullptr, nullptr, nullptr};
    const int*   masks[2] = {nullptr, nullptr};
    const float* Ws[4]    = {nullptr, nullptr, nullptr, nullptr};
    const float* bs[4]    = {nullptr, nullptr, nullptr, nullptr};
    int nqkv = 0, nmask = 0, nW = 0, nb = 0;
    for (int i = 0; i < n_in; i++) {
        int sz = in_sizes[i];
        if (sz == MTOT * DD && nqkv < 3)      qkv[nqkv++] = (const float*)d_in[i];
        else if (sz == MTOT && nmask < 2)     masks[nmask++] = (const int*)d_in[i];
        else if (sz == DD * DD && nW < 4)     Ws[nW++] = (const float*)d_in[i];
        else if (sz == DD && nb < 4)          bs[nb++] = (const float*)d_in[i];
    }

    static int attr_done = 0;
    if (!attr_done) {
        cudaFuncSetAttribute(gemm_mma_kernel,
                             cudaFuncAttributeMaxDynamicSharedMemorySize, GSM2_BYTES);
        cudaFuncSetAttribute(attn_mma_kernel,
                             cudaFuncAttributeMaxDynamicSharedMemorySize, ATTN_SMEM);
        attr_done = 1;
    }

    int *gidx, *gcnt;
    __half *gq, *gk, *gv, *gW, *gpq, *gpk, *gpv, *ga;
    cudaGetSymbolAddress((void**)&gidx, g_idx);
    cudaGetSymbolAddress((void**)&gcnt, g_cnt);
    cudaGetSymbolAddress((void**)&gq, g_q);
    cudaGetSymbolAddress((void**)&gk, g_k);
    cudaGetSymbolAddress((void**)&gv, g_v);
    cudaGetSymbolAddress((void**)&gW, g_W);
    cudaGetSymbolAddress((void**)&gpq, g_pq);
    cudaGetSymbolAddress((void**)&gpk, g_pk);
    cudaGetSymbolAddress((void**)&gpv, g_pv);
    cudaGetSymbolAddress((void**)&ga, g_a);

    const int N8_ACT = (int)(ACT / 8);
    const int N8_W   = (int)(WN / 8);

    build_idx_kernel<<<BB, 1024>>>(masks[0], masks[1], gidx, gcnt);

    {
        ConvHArgs aa = {};
        aa.src[0] = qkv[0]; aa.dst[0] = gq;
        aa.src[1] = qkv[1]; aa.dst[1] = gk;
        aa.src[2] = qkv[2]; aa.dst[2] = gv;
        conv_half_multi<<<dim3((N8_ACT + 255) / 256, 3), 256>>>(aa, N8_ACT);

        ConvWArgs wa = {};
        for (int w = 0; w < 4; w++) {
            wa.src[w] = Ws[w];
            wa.hi[w]  = gW + (size_t)w * 2 * WN;
            wa.lo[w]  = gW + (size_t)w * 2 * WN + WN;
        }
        conv_wsplit_multi<<<dim3((N8_W + 255) / 256, 4), 256>>>(wa, N8_W);
    }

    const float QSCALE = 0.125f * 1.4426950408889634f;
    gemm_mma_kernel<<<dim3(DD / 128, MTOT / 256, 3), 512, GSM2_BYTES>>>(
        gq, gk, gv, gW, bs[0], bs[1], bs[2], QSCALE,
        nullptr, gpq, gpk, gpv, gidx, gcnt, 0b110);

    attn_mma_kernel<<<dim3(SS / 128, HH, BB), 256, ATTN_SMEM>>>(
        gpq, gpk, gpv, ga, gcnt);

    gemm_mma_kernel<<<dim3(DD / 128, MTOT / 256, 1), 512, GSM2_BYTES>>>(
        ga, ga, ga, gW + (size_t)3 * 2 * WN, bs[3], bs[3], bs[3], 1.0f,
        (float*)d_out, nullptr, nullptr, nullptr, nullptr, nullptr, 0);
}

// round 17
// speedup vs baseline: 1.4820x; 1.4820x over previous
#include <cuda_runtime.h>
#include <cuda_bf16.h>
#include <cuda_fp16.h>
#include <cstdint>
#include <cstddef>

// Problem constants
#define BB 2
#define SS 2048
#define DD 1024
#define HH 16
#define HDIM 64
#define MTOT (BB * SS) // 4096

#define ACT ((size_t)MTOT * DD)  // 4194304 elements
#define WN  ((size_t)DD * DD)    // 1048576 elements

// ---------------------------------------------------------------------------
// Scratch (device globals)
// ---------------------------------------------------------------------------
__device__ int g_idx[MTOT];
__device__ int g_cnt[BB];
__device__ __half g_q[MTOT * DD];          // fp16 activations
__device__ __half g_k[MTOT * DD];
__device__ __half g_v[MTOT * DD];
__device__ __half g_W[4][DD * DD];         // fp16 single-plane weights
__device__ __half g_pq[MTOT * DD];         // projected Q/K/V, fp16
__device__ __half g_pk[MTOT * DD];
__device__ __half g_pv[MTOT * DD];
__device__ __half g_a[MTOT * DD];          // attention output, fp16

// ---------------------------------------------------------------------------
// PTX helpers
// ---------------------------------------------------------------------------
__device__ __forceinline__ void cp16(unsigned dst, const void* src) {
    asm volatile("cp.async.cg.shared.global [%0], [%1], 16;" :: "r"(dst), "l"(src));
}
__device__ __forceinline__ void cp_commit() { asm volatile("cp.async.commit_group;"); }
__device__ __forceinline__ void cp_wait0()  { asm volatile("cp.async.wait_group 0;" ::: "memory"); }

__device__ __forceinline__ void ldmx4(uint32_t* r, uint32_t addr) {
    asm volatile("ldmatrix.sync.aligned.m8n8.x4.shared.b16 {%0,%1,%2,%3}, [%4];"
                 : "=r"(r[0]), "=r"(r[1]), "=r"(r[2]), "=r"(r[3]) : "r"(addr));
}
__device__ __forceinline__ void ldmx4t(uint32_t* r, uint32_t addr) {
    asm volatile("ldmatrix.sync.aligned.m8n8.x4.trans.shared.b16 {%0,%1,%2,%3}, [%4];"
                 : "=r"(r[0]), "=r"(r[1]), "=r"(r[2]), "=r"(r[3]) : "r"(addr));
}
__device__ __forceinline__ void mma_f16(float* d, const uint32_t* a, const uint32_t* b) {
    asm volatile(
        "mma.sync.aligned.m16n8k16.row.col.f32.f16.f16.f32 "
        "{%0,%1,%2,%3}, {%4,%5,%6,%7}, {%8,%9}, {%0,%1,%2,%3};"
        : "+f"(d[0]), "+f"(d[1]), "+f"(d[2]), "+f"(d[3])
        : "r"(a[0]), "r"(a[1]), "r"(a[2]), "r"(a[3]), "r"(b[0]), "r"(b[1]));
}
__device__ __forceinline__ float ex2(float x) {
    float r;
    asm("ex2.approx.f32 %0, %1;" : "=f"(r) : "f"(x));
    return r;
}

// ---------------------------------------------------------------------------
// Conv kernel: fp32 -> fp16, up to 8 tensors in one launch (per-slot sizes)
// ---------------------------------------------------------------------------
struct ConvHArgs {
    const float* src[8];
    __half* dst[8];
    int n8[8];
};
__global__ __launch_bounds__(256) void conv_half_multi(ConvHArgs a)
{
    const int y = blockIdx.y;
    int i = blockIdx.x * blockDim.x + threadIdx.x;
    if (i >= a.n8[y]) return;
    const float* x = a.src[y];
    float4 v0 = ((const float4*)x)[2 * i];
    float4 v1 = ((const float4*)x)[2 * i + 1];
    __half2 h0 = __floats2half2_rn(v0.x, v0.y);
    __half2 h1 = __floats2half2_rn(v0.z, v0.w);
    __half2 h2 = __floats2half2_rn(v1.x, v1.y);
    __half2 h3 = __floats2half2_rn(v1.z, v1.w);
    ((uint4*)a.dst[y])[i] = make_uint4(*(uint32_t*)&h0, *(uint32_t*)&h1,
                                       *(uint32_t*)&h2, *(uint32_t*)&h3);
}

// ---------------------------------------------------------------------------
// Kernel 1: deterministic mask compaction
// ---------------------------------------------------------------------------
__global__ __launch_bounds__(1024) void build_idx_kernel(
    const int* __restrict__ kp, const int* __restrict__ am,
    int* __restrict__ idx, int* __restrict__ counts)
{
    __shared__ int ssum[1024];
    const int b = blockIdx.x;
    const int t = threadIdx.x;
    const int base = b * SS;
    const int s0 = 2 * t, s1 = 2 * t + 1;
    int v0 = (kp[base + s0] == 0 && am[base + s0] == 0) ? 1 : 0;
    int v1 = (kp[base + s1] == 0 && am[base + s1] == 0) ? 1 : 0;
    ssum[t] = v0 + v1;
    __syncthreads();
    for (int off = 1; off < 1024; off <<= 1) {
        int add = (t >= off) ? ssum[t - off] : 0;
        int val = ssum[t];
        __syncthreads();
        ssum[t] = val + add;
        __syncthreads();
    }
    int excl = ssum[t] - (v0 + v1);
    if (v0) idx[base + excl]      = base + s0;
    if (v1) idx[base + excl + v0] = base + s1;
    if (t == 1023) counts[b] = ssum[1023];
}

// ---------------------------------------------------------------------------
// Kernel 2: f16 HMMA GEMM, tile 256x128, BK=64, 512 threads.
// A fp16 via cp.async smem (round-15 path), W fp16 SINGLE plane.
// Smem per stage: A 32K | W 16K = 48KB; x2 stages = 96KB.
// ---------------------------------------------------------------------------
#define GSTAGE2 49152
#define GSM2_BYTES (2 * GSTAGE2)

__global__ __launch_bounds__(512, 1) void gemm_mma_kernel(
    const __half* __restrict__ A0, const __half* __restrict__ A1,
    const __half* __restrict__ A2,
    const __half* __restrict__ Wb,          // weight z at Wb + z*WN
    const float* __restrict__ b0, const float* __restrict__ b1,
    const float* __restrict__ b2,
    float s0,
    float* __restrict__ Cf,
    __half* __restrict__ C0, __half* __restrict__ C1, __half* __restrict__ C2,
    const int* __restrict__ gather, const int* __restrict__ counts, int gmask)
{
    extern __shared__ char smem[];
    const uint32_t sb = (uint32_t)__cvta_generic_to_shared(smem);
    const int z = blockIdx.z;
    const __half* Ain = (z == 0) ? A0 : (z == 1) ? A1 : A2;
    const __half* Whi = Wb + (size_t)z * WN;
    const float* bias = (z == 0) ? b0 : (z == 1) ? b1 : b2;
    __half* Ch = (z == 0) ? C0 : (z == 1) ? C1 : C2;
    const float scale = (z == 0) ? s0 : 1.0f;
    const bool useG = ((gmask >> z) & 1) != 0;

    const int nBase = blockIdx.x * 128;
    const int mBase = blockIdx.y * 256;
    int cnt = 0;
    if (useG) {
        cnt = counts[mBase >> 11];
        if ((mBase & 2047) >= cnt) return;
    }
    const int t = threadIdx.x;
    const int wid = t >> 5, lane = t & 31;
    const int wm = wid >> 1;
    const int wn = wid & 1;

    // A staging: row t>>1 (0..255), units (t&1)*4 + i
    const int sRow = t >> 1, uA = (t & 1) * 4;
    int srcRow;
    {
        int m = mBase + sRow;
        if (useG) {
            bool ok = (m & 2047) < cnt;
            srcRow = ok ? gather[m] : ((m >> 11) * SS);
        } else {
            srcRow = m;
        }
    }
    const __half* aHp = Ain + (size_t)srcRow * DD;
    // W staging: row t>>2 (0..127), units (t&3)*2 + i
    const int sRowW = t >> 2, uW = (t & 3) * 2;
    const __half* bHp = Whi + (size_t)(nBase + sRowW) * DD;

    const int g  = lane >> 3;
    const int lr = lane & 7;
    const uint32_t rowA = wm * 32 + (g & 1) * 8 + lr;
    const uint32_t rxa  = rowA & 7;
    const uint32_t aoff = rowA * 128;
    const int aU = g >> 1;
    const uint32_t rowB = wn * 64 + (g >> 1) * 8 + lr;
    const uint32_t rxb  = rowB & 7;
    const uint32_t boff = rowB * 128;
    const int bU = g & 1;

    float acc[2][8][4];
#pragma unroll
    for (int mt = 0; mt < 2; mt++)
#pragma unroll
        for (int j = 0; j < 8; j++)
#pragma unroll
            for (int r = 0; r < 4; r++) acc[mt][j][r] = 0.f;

    // smem layout per stage: A 0..32K, W 32K..48K
    auto stage = [&](int s, int k0) {
        const uint32_t bb = sb + s * GSTAGE2;
#pragma unroll
        for (int i = 0; i < 4; i++) {
            int u = uA + i;
            uint32_t sw = sRow * 128 + ((u ^ (sRow & 7)) << 4);
            cp16(bb + sw, aHp + k0 + u * 8);
        }
#pragma unroll
        for (int i = 0; i < 2; i++) {
            int u = uW + i;
            uint32_t sw = sRowW * 128 + ((u ^ (sRowW & 7)) << 4);
            cp16(bb + 32768 + sw, bHp + k0 + u * 8);
        }
        cp_commit();
    };
    stage(0, 0);

    for (int c = 0; c < 16; c++) {
        cp_wait0();
        __syncthreads();
        if (c + 1 < 16) stage((c + 1) & 1, (c + 1) * 64);

        const uint32_t base = sb + (c & 1) * GSTAGE2;
#pragma unroll
        for (int ks = 0; ks < 4; ks++) {
            uint32_t ah[2][4];
#pragma unroll
            for (int mt = 0; mt < 2; mt++) {
                uint32_t sw = ((2 * ks + aU) ^ rxa) << 4;
                ldmx4(ah[mt], base + aoff + mt * 2048 + sw);
            }
#pragma unroll
            for (int jp = 0; jp < 4; jp++) {
                uint32_t sw = ((2 * ks + bU) ^ rxb) << 4;
                uint32_t rh[4];
                ldmx4(rh, base + 32768 + boff + jp * 2048 + sw);
                mma_f16(acc[0][2 * jp],     ah[0], rh);
                mma_f16(acc[1][2 * jp],     ah[1], rh);
                mma_f16(acc[0][2 * jp + 1], ah[0], rh + 2);
                mma_f16(acc[1][2 * jp + 1], ah[1], rh + 2);
            }
        }
        __syncthreads();
    }

#pragma unroll
    for (int mt = 0; mt < 2; mt++) {
        int m0 = mBase + wm * 32 + mt * 16 + (lane >> 2);
        int m1 = m0 + 8;
        bool ok0 = true, ok1 = true;
        if (useG) {
            ok0 = (m0 & 2047) < cnt;
            ok1 = (m1 & 2047) < cnt;
        }
#pragma unroll
        for (int j = 0; j < 8; j++) {
            int n = nBase + wn * 64 + j * 8 + 2 * (lane & 3);
            float b0v = bias[n], b1v = bias[n + 1];
            float o00 = (acc[mt][j][0] + b0v) * scale;
            float o01 = (acc[mt][j][1] + b1v) * scale;
            float o10 = (acc[mt][j][2] + b0v) * scale;
            float o11 = (acc[mt][j][3] + b1v) * scale;
            if (Cf) {
                if (ok0) *(float2*)&Cf[(size_t)m0 * DD + n] = make_float2(o00, o01);
                if (ok1) *(float2*)&Cf[(size_t)m1 * DD + n] = make_float2(o10, o11);
            } else {
                if (ok0) *(__half2*)&Ch[(size_t)m0 * DD + n] = __floats2half2_rn(o00, o01);
                if (ok1) *(__half2*)&Ch[(size_t)m1 * DD + n] = __floats2half2_rn(o10, o11);
            }
        }
    }
}

// ---------------------------------------------------------------------------
// Kernel 3: tensor-core flash attention — fp16 single-plane Q/K/V/P.
// (unchanged from round 15)
// ---------------------------------------------------------------------------
#define ASM_K 0
#define ASM_V 16384
#define ATTN_SMEM 32768

__global__ __launch_bounds__(256, 2) void attn_mma_kernel(
    const __half* __restrict__ Q_, const __half* __restrict__ K_,
    const __half* __restrict__ V_, __half* __restrict__ O_,
    const int* __restrict__ counts)
{
    extern __shared__ char smem[];
    const uint32_t sb = (uint32_t)__cvta_generic_to_shared(smem);
    const int qb = blockIdx.x, h = blockIdx.y, b = blockIdx.z;
    const int t = threadIdx.x, w = t >> 5, lane = t & 31;
    const int q0 = qb * 128;
    const int cnt = counts[b];
    const int nb = (cnt + 63) >> 6;
    const size_t hoff = (size_t)h * HDIM;

    const int g  = lane >> 3;
    const int lr = lane & 7;
    const uint32_t rowA = w * 16 + (g & 1) * 8 + lr;
    const uint32_t rxa  = rowA & 7;
    const uint32_t aoff = rowA * 128;
    const int aU = g >> 1;
    const uint32_t rowB = (g >> 1) * 8 + lr;
    const uint32_t rxb  = rowB & 7;
    const int bU = g & 1;
    const uint32_t rowV = (g & 1) * 8 + lr;
    const uint32_t rxv  = rowV & 7;
    const int vU = g >> 1;

    {
        const int sRowQ = t >> 1, uBQ = (t & 1) * 4;
        const __half* qp = Q_ + (size_t)(b * SS + q0 + sRowQ) * DD + hoff;
#pragma unroll
        for (int i = 0; i < 4; i++) {
            int u = uBQ + i;
            uint32_t off = sRowQ * 128 + ((u ^ (sRowQ & 7)) << 4);
            cp16(sb + off, qp + u * 8);
        }
        cp_commit();
    }
    cp_wait0();
    __syncthreads();

    uint32_t qa[4][4];
#pragma unroll
    for (int ks = 0; ks < 4; ks++) {
        const uint32_t swA = ((2 * ks + aU) ^ rxa) << 4;
        ldmx4(qa[ks], sb + aoff + swA);
    }
    __syncthreads();

    const int sRowK = t >> 2, uBK = (t & 3) * 2;
    auto stage_kv = [&](int bufI, int kbase) {
        const size_t rb = (size_t)(b * SS + kbase + sRowK) * DD + hoff;
        const uint32_t o = bufI * 8192;
#pragma unroll
        for (int i = 0; i < 2; i++) {
            int u = uBK + i;
            uint32_t sw = sRowK * 128 + ((u ^ (sRowK & 7)) << 4);
            cp16(sb + ASM_K + o + sw, K_ + rb + u * 8);
            cp16(sb + ASM_V + o + sw, V_ + rb + u * 8);
        }
    };
    stage_kv(0, 0);
    cp_commit();

    float m0 = -1e30f, m1 = -1e30f, l0 = 0.f, l1 = 0.f;
    float oacc[8][4];
#pragma unroll
    for (int j = 0; j < 8; j++)
#pragma unroll
        for (int r = 0; r < 4; r++) oacc[j][r] = 0.f;

    int buf = 0;
    for (int kb = 0; kb < nb; kb++) {
        cp_wait0();
        __syncthreads();
        if (kb + 1 < nb) {
            stage_kv(buf ^ 1, (kb + 1) * 64);
            cp_commit();
        }

        const uint32_t tK = sb + ASM_K + buf * 8192;

        float sacc[8][4];
#pragma unroll
        for (int j = 0; j < 8; j++)
#pragma unroll
            for (int r = 0; r < 4; r++) sacc[j][r] = 0.f;
#pragma unroll
        for (int ks = 0; ks < 4; ks++) {
#pragma unroll
            for (int jp = 0; jp < 4; jp++) {
                const uint32_t addr = (rowB + 16 * jp) * 128 + (((2 * ks + bU) ^ rxb) << 4);
                uint32_t rh[4];
                ldmx4(rh, tK + addr);
                mma_f16(sacc[2 * jp],     qa[ks], rh);
                mma_f16(sacc[2 * jp + 1], qa[ks], rh + 2);
            }
        }

        const int kcol = kb * 64 + 2 * (lane & 3);
#pragma unroll
        for (int j = 0; j < 8; j++) {
            const int kc = kcol + 8 * j;
            if (kc >= cnt)     { sacc[j][0] = -1e30f; sacc[j][2] = -1e30f; }
            if (kc + 1 >= cnt) { sacc[j][1] = -1e30f; sacc[j][3] = -1e30f; }
        }

        float rm0 = -1e30f, rm1 = -1e30f;
#pragma unroll
        for (int j = 0; j < 8; j++) {
            rm0 = fmaxf(rm0, fmaxf(sacc[j][0], sacc[j][1]));
            rm1 = fmaxf(rm1, fmaxf(sacc[j][2], sacc[j][3]));
        }
        rm0 = fmaxf(rm0, __shfl_xor_sync(0xffffffffu, rm0, 1));
        rm0 = fmaxf(rm0, __shfl_xor_sync(0xffffffffu, rm0, 2));
        rm1 = fmaxf(rm1, __shfl_xor_sync(0xffffffffu, rm1, 1));
        rm1 = fmaxf(rm1, __shfl_xor_sync(0xffffffffu, rm1, 2));
        const float nm0 = fmaxf(m0, rm0), nm1 = fmaxf(m1, rm1);
        const float c0 = ex2(m0 - nm0), c1 = ex2(m1 - nm1);
        m0 = nm0; m1 = nm1;
        float rs0 = 0.f, rs1 = 0.f;
#pragma unroll
        for (int j = 0; j < 8; j++) {
            sacc[j][0] = ex2(sacc[j][0] - nm0);
            sacc[j][1] = ex2(sacc[j][1] - nm0);
            sacc[j][2] = ex2(sacc[j][2] - nm1);
            sacc[j][3] = ex2(sacc[j][3] - nm1);
            rs0 += sacc[j][0] + sacc[j][1];
            rs1 += sacc[j][2] + sacc[j][3];
        }
        rs0 += __shfl_xor_sync(0xffffffffu, rs0, 1);
        rs0 += __shfl_xor_sync(0xffffffffu, rs0, 2);
        rs1 += __shfl_xor_sync(0xffffffffu, rs1, 1);
        rs1 += __shfl_xor_sync(0xffffffffu, rs1, 2);
        l0 = l0 * c0 + rs0;
        l1 = l1 * c1 + rs1;
#pragma unroll
        for (int j = 0; j < 8; j++) {
            oacc[j][0] *= c0; oacc[j][1] *= c0;
            oacc[j][2] *= c1; oacc[j][3] *= c1;
        }

        const uint32_t tV = sb + ASM_V + buf * 8192;
#pragma unroll
        for (int ks = 0; ks < 4; ks++) {
            const int nt0 = 2 * ks, nt1 = 2 * ks + 1;
            uint32_t aP[4];
            {
                __half2 p0 = __floats2half2_rn(sacc[nt0][0], sacc[nt0][1]);
                __half2 p1 = __floats2half2_rn(sacc[nt0][2], sacc[nt0][3]);
                __half2 p2 = __floats2half2_rn(sacc[nt1][0], sacc[nt1][1]);
                __half2 p3 = __floats2half2_rn(sacc[nt1][2], sacc[nt1][3]);
                aP[0] = *(uint32_t*)&p0; aP[1] = *(uint32_t*)&p1;
                aP[2] = *(uint32_t*)&p2; aP[3] = *(uint32_t*)&p3;
            }
#pragma unroll
            for (int dp = 0; dp < 4; dp++) {
                const uint32_t addr = (rowV + 16 * ks) * 128 + (((2 * dp + vU) ^ rxv) << 4);
                uint32_t rv[4];
                ldmx4t(rv, tV + addr);
                mma_f16(oacc[2 * dp],     aP, rv);
                mma_f16(oacc[2 * dp + 1], aP, rv + 2);
            }
        }
        buf ^= 1;
    }

    const float inv0 = 1.0f / l0, inv1 = 1.0f / l1;
    const int row0 = b * SS + q0 + w * 16 + (lane >> 2);
    const int row1 = row0 + 8;
    const int dbase = h * HDIM + 2 * (lane & 3);
#pragma unroll
    for (int j = 0; j < 8; j++) {
        size_t a0 = (size_t)row0 * DD + dbase + 8 * j;
        size_t a1 = (size_t)row1 * DD + dbase + 8 * j;
        *(__half2*)&O_[a0] = __floats2half2_rn(oacc[j][0] * inv0, oacc[j][1] * inv0);
        *(__half2*)&O_[a1] = __floats2half2_rn(oacc[j][2] * inv1, oacc[j][3] * inv1);
    }
}

// ---------------------------------------------------------------------------
// Launch
// ---------------------------------------------------------------------------
extern "C" void kernel_launch(void* const* d_in, const int* in_sizes, int n_in,
                              void* d_out, int out_size)
{
    (void)out_size;
    const float* qkv[3]   = {nullptr, nullptr, nullptr};
    const int*   masks[2] = {nullptr, nullptr};
    const float* Ws[4]    = {nullptr, nullptr, nullptr, nullptr};
    const float* bs[4]    = {nullptr, nullptr, nullptr, nullptr};
    int nqkv = 0, nmask = 0, nW = 0, nb = 0;
    for (int i = 0; i < n_in; i++) {
        int sz = in_sizes[i];
        if (sz == MTOT * DD && nqkv < 3)      qkv[nqkv++] = (const float*)d_in[i];
        else if (sz == MTOT && nmask < 2)     masks[nmask++] = (const int*)d_in[i];
        else if (sz == DD * DD && nW < 4)     Ws[nW++] = (const float*)d_in[i];
        else if (sz == DD && nb < 4)          bs[nb++] = (const float*)d_in[i];
    }

    static int attr_done = 0;
    if (!attr_done) {
        cudaFuncSetAttribute(gemm_mma_kernel,
                             cudaFuncAttributeMaxDynamicSharedMemorySize, GSM2_BYTES);
        cudaFuncSetAttribute(attn_mma_kernel,
                             cudaFuncAttributeMaxDynamicSharedMemorySize, ATTN_SMEM);
        attr_done = 1;
    }

    int *gidx, *gcnt;
    __half *gq, *gk, *gv, *gW, *gpq, *gpk, *gpv, *ga;
    cudaGetSymbolAddress((void**)&gidx, g_idx);
    cudaGetSymbolAddress((void**)&gcnt, g_cnt);
    cudaGetSymbolAddress((void**)&gq, g_q);
    cudaGetSymbolAddress((void**)&gk, g_k);
    cudaGetSymbolAddress((void**)&gv, g_v);
    cudaGetSymbolAddress((void**)&gW, g_W);
    cudaGetSymbolAddress((void**)&gpq, g_pq);
    cudaGetSymbolAddress((void**)&gpk, g_pk);
    cudaGetSymbolAddress((void**)&gpv, g_pv);
    cudaGetSymbolAddress((void**)&ga, g_a);

    const int N8_ACT = (int)(ACT / 8);
    const int N8_W   = (int)(WN / 8);

    build_idx_kernel<<<BB, 1024>>>(masks[0], masks[1], gidx, gcnt);

    // single batched conversion launch: 3 activations + 4 weights
    {
        ConvHArgs aa = {};
        aa.src[0] = qkv[0]; aa.dst[0] = gq; aa.n8[0] = N8_ACT;
        aa.src[1] = qkv[1]; aa.dst[1] = gk; aa.n8[1] = N8_ACT;
        aa.src[2] = qkv[2]; aa.dst[2] = gv; aa.n8[2] = N8_ACT;
        for (int w = 0; w < 4; w++) {
            aa.src[3 + w] = Ws[w];
            aa.dst[3 + w] = gW + (size_t)w * WN;
            aa.n8[3 + w]  = N8_W;
        }
        conv_half_multi<<<dim3((N8_ACT + 255) / 256, 7), 256>>>(aa);
    }

    const float QSCALE = 0.125f * 1.4426950408889634f;
    gemm_mma_kernel<<<dim3(DD / 128, MTOT / 256, 3), 512, GSM2_BYTES>>>(
        gq, gk, gv, gW, bs[0], bs[1], bs[2], QSCALE,
        nullptr, gpq, gpk, gpv, gidx, gcnt, 0b110);

    attn_mma_kernel<<<dim3(SS / 128, HH, BB), 256, ATTN_SMEM>>>(
        gpq, gpk, gpv, ga, gcnt);

    gemm_mma_kernel<<<dim3(DD / 128, MTOT / 256, 1), 512, GSM2_BYTES>>>(
        ga, ga, ga, gW + (size_t)3 * WN, bs[3], bs[3], bs[3], 1.0f,
        (float*)d_out, nullptr, nullptr, nullptr, nullptr, nullptr, 0);
}